// round 17
// baseline (speedup 1.0000x reference)
#include <cuda_runtime.h>

constexpr int Nn = 4096;   // z rows
constexpr int Mm = 1024;   // e rows
constexpr int Dd = 64;     // feature dim

constexpr int NH = 2048;                     // z-half per NN block
constexpr int BK = 2048;                     // buckets per half
constexpr float LOb  = -6.0f;
constexpr float HIb  =  6.0f;
constexpr float INVW = BK / (HIb - LOb);

__device__ __forceinline__ int bucket_of(float v) {
    int k = (int)((v - LOb) * INVW);
    return min(max(k, 0), BK - 1);
}

// Scratch (no allocations allowed -> device globals)
__device__ __align__(16) float g_zt[Dd * Nn];    // z transposed: [D][N]
__device__ __align__(16) float g_et[Dd * Mm];    // e transposed: [D][M]
__device__ float g_pb0[Dd * Mm];                 // per-query best, half 0
__device__ float g_pb1[Dd * Mm];                 // per-query best, half 1
__device__ int   g_tick[Dd];                     // per-column tickets (0 at rest)

// ---------------------------------------------------------------------------
// k1: pure transposes, ONE 32x32 tile per block (no serialization).
// Grid (2, 160): by<128 -> z tile into g_zt; by>=128 -> e tile into g_et.
__global__ void k1_prep(const float* __restrict__ z, const float* __restrict__ e,
                        float* __restrict__ out) {
    __shared__ float tile[32][33];
    int bx = blockIdx.x, by = blockIdx.y;
    int tx = threadIdx.x, ty = threadIdx.y;

    if (by < 128) {
        int x = bx * 32 + tx;            // D index
        int y = by * 32 + ty;            // N index
        tile[ty][tx] = z[y * Dd + x];
        if (bx == 0 && by == 0 && tx == 0 && ty == 0) out[0] = 0.0f;
        __syncthreads();
        g_zt[(bx * 32 + ty) * Nn + by * 32 + tx] = tile[tx][ty];
    } else {
        int v = (by - 128) * 2 + bx;     // 0..63 e-tile unit
        int dh = v & 1, mt = v >> 1;
        int x = dh * 32 + tx;            // D index
        int m = mt * 32 + ty;            // M index
        tile[ty][tx] = e[m * Dd + x];
        __syncthreads();
        g_et[(dh * 32 + ty) * Mm + mt * 32 + tx] = tile[tx][ty];
    }
}

// ---------------------------------------------------------------------------
// k2: 160 blocks. bx<128: NN half-block (d = bx>>1, h = bx&1) — build bucket
// structure over its 2048-value half (coalesced from g_zt), query all 1024
// e's (coalesced from g_et), store bests to its g_pb array; second finisher
// per column combines (reads peer bests from L2), reduces, atomicAdd out[0].
// bx>=128: mask + copy blocks (independent).
__global__ void __launch_bounds__(1024) k2_nn(const float* __restrict__ z,
                                              const int* __restrict__ idx,
                                              float* __restrict__ out) {
    const int bx = blockIdx.x;
    const int t  = threadIdx.x;

    if (bx >= 128) {
        // ---------------- mask + copy block ----------------
        const int cb = bx - 128;             // 0..31
        #pragma unroll
        for (int i = 0; i < 2; i++) {
            int gid = cb * 2048 + i * 1024 + t;      // float4 index
            int row = gid >> 4;
            int col = (gid & 15) * 4;
            float4 v = reinterpret_cast<const float4*>(z)[gid];
            int k = idx[row];
            int base = gid * 4;
            out[1 + base + 0] = (col + 0 < k) ? v.x : 0.0f;
            out[1 + base + 1] = (col + 1 < k) ? v.y : 0.0f;
            out[1 + base + 2] = (col + 2 < k) ? v.z : 0.0f;
            out[1 + base + 3] = (col + 3 < k) ? v.w : 0.0f;
            out[1 + Nn * Dd + base + 0] = v.x;
            out[1 + Nn * Dd + base + 1] = v.y;
            out[1 + Nn * Dd + base + 2] = v.z;
            out[1 + Nn * Dd + base + 3] = v.w;
        }
        return;
    }

    // ---------------- NN half-block ----------------
    __shared__ float S[NH];          // bucket-grouped half-column (8 KB)
    __shared__ int   cnt[BK];        // hist -> exclusive starts (8 KB)
    __shared__ int   wtot[32];
    __shared__ float red[32];
    __shared__ int   is_comb;

    const int d = bx >> 1;
    const int h = bx & 1;
    const int lane = t & 31, wid = t >> 5;

    // Coalesced prefetches.
    float x = g_et[d * Mm + t];
    float2 vv = reinterpret_cast<const float2*>(g_zt + d * Nn + h * NH)[t];

    cnt[t] = 0; cnt[t + 1024] = 0;
    __syncthreads();

    // ---- single atomic pass: histogram + within-bucket rank ----
    int b0 = bucket_of(vv.x), b1 = bucket_of(vv.y);
    int r0 = atomicAdd(&cnt[b0], 1);
    int r1 = atomicAdd(&cnt[b1], 1);
    __syncthreads();

    // ---- block exclusive scan (2 buckets per thread) ----
    int c0 = cnt[2 * t], c1 = cnt[2 * t + 1];
    int s = c0 + c1;
    int inc = s;
    #pragma unroll
    for (int o = 1; o < 32; o <<= 1) {
        int n = __shfl_up_sync(0xFFFFFFFFu, inc, o);
        if (lane >= o) inc += n;
    }
    if (lane == 31) wtot[wid] = inc;
    __syncthreads();
    if (wid == 0) {
        int ws = wtot[lane];
        int wi = ws;
        #pragma unroll
        for (int o = 1; o < 32; o <<= 1) {
            int n = __shfl_up_sync(0xFFFFFFFFu, wi, o);
            if (lane >= o) wi += n;
        }
        wtot[lane] = wi - ws;            // exclusive warp offsets
    }
    __syncthreads();
    int excl = (inc - s) + wtot[wid];
    cnt[2 * t]     = excl;
    cnt[2 * t + 1] = excl + c0;
    __syncthreads();

    // ---- scatter: plain stores (start + rank unique) ----
    S[cnt[b0] + r0] = vv.x;
    S[cnt[b1] + r1] = vv.y;
    __syncthreads();

    // ---- query: own bucket + nearest nonempty bucket each side ----
    int k0 = bucket_of(x);
    int start = cnt[k0];
    int end   = (k0 < BK - 1) ? cnt[k0 + 1] : NH;

    float best = 1e30f;
    for (int j = start; j < end; j++)
        best = fminf(best, fabsf(S[j] - x));

    if (start > 0) {                     // nearest nonempty bucket below
        int bb = bucket_of(S[start - 1]);
        int lo = cnt[bb];
        for (int j = lo; j < start; j++)
            best = fminf(best, fabsf(S[j] - x));
    }
    if (end < NH) {                      // nearest nonempty bucket above
        int bb = bucket_of(S[end]);
        int hi = (bb < BK - 1) ? cnt[bb + 1] : NH;
        for (int j = end; j < hi; j++)
            best = fminf(best, fabsf(S[j] - x));
    }

    // ---- publish own half's bests, second finisher combines ----
    if (h == 0) g_pb0[d * Mm + t] = best;
    else        g_pb1[d * Mm + t] = best;
    __threadfence();                     // make stores GPU-visible
    __syncthreads();
    if (t == 0) {
        int old = atomicAdd(&g_tick[d], 1);
        is_comb = (old == 1);            // second finisher combines
    }
    __syncthreads();
    if (!is_comb) return;

    const float* peer = (h == 0) ? &g_pb1[d * Mm] : &g_pb0[d * Mm];
    float pm = __ldcg(&peer[t]);
    float m = fminf(best, pm);
    float val = m * m * (1.0f / (float)(Mm * Dd));
    #pragma unroll
    for (int o = 16; o > 0; o >>= 1)
        val += __shfl_xor_sync(0xFFFFFFFFu, val, o);
    if (lane == 0) red[wid] = val;
    __syncthreads();
    if (wid == 0) {
        float sv = red[lane];
        #pragma unroll
        for (int o = 16; o > 0; o >>= 1)
            sv += __shfl_xor_sync(0xFFFFFFFFu, sv, o);
        if (lane == 0) {
            atomicAdd(out, sv);
            g_tick[d] = 0;               // reset for next graph replay
        }
    }
}

// ---------------------------------------------------------------------------
extern "C" void kernel_launch(void* const* d_in, const int* in_sizes, int n_in,
                              void* d_out, int out_size) {
    const float* z = (const float*)d_in[0];
    const float* e = (const float*)d_in[1];
    const int* idx = (const int*)d_in[2];
    float* out = (float*)d_out;

    k1_prep<<<dim3(2, 160), dim3(32, 32)>>>(z, e, out);
    k2_nn<<<160, 1024>>>(z, idx, out);
}